// round 10
// baseline (speedup 1.0000x reference)
#include <cuda_runtime.h>
#include <cuda_bf16.h>
#include <cstdint>

static constexpr int N   = 256;
static constexpr int B   = 512;
static constexpr int M   = N * (N - 1) / 2;   // 32640 (multiple of 4)
static constexpr int TPB = 64;                // threads = batch streams per block
static constexpr int TJ  = 64;                // output columns per tile (aligned)
static constexpr long long NN = (long long)N * N;

__device__ __forceinline__ float sqrt_approx(float x) {
    float r;
    asm("sqrt.approx.f32 %0, %1;" : "=f"(r) : "f"(x));
    return r;
}

// Reference recurrence step. x2 = fma(-z2, rowsum, z2) = z2*(1-rowsum) in one
// rounding: bit-identical to the reference wherever rowsum >= 0.5 (Sterbenz:
// 1-rowsum exact), which covers the deep-column plateau; <=1 ulp below that.
__device__ __forceinline__ float chol_step(float z, float& rs) {
    float z2 = __fmul_rn(z, z);
    float x2 = __fmaf_rn(-z2, rs, z2);
    rs       = __fadd_rn(rs, x2);
    return copysignf(sqrt_approx(x2), z);
}

__device__ __forceinline__ uint32_t su32(const void* p) {
    return (uint32_t)__cvta_generic_to_shared(p);
}
// 16B async copy; copies szb (0..16) bytes from 16B-aligned src, zero-fills rest.
__device__ __forceinline__ void cp16(uint32_t dst, const float* src, int szb) {
    asm volatile("cp.async.cg.shared.global [%0], [%1], 16, %2;\n"
                 :: "r"(dst), "l"(src), "r"(szb));
}
#define CP_COMMIT() asm volatile("cp.async.commit_group;\n")
#define CP_WAIT0()  asm volatile("cp.async.wait_group 0;\n" ::: "memory")

// Input smem layout: quad slot(bb, q) = q*64 + ((bb+q)&63). Conflict-free for
// cp.async writes (lanes span q), per-thread LDS.128 (lanes span bb, rotated
// contiguous), and store-phase LDS.128 (lanes span q, group (bb+q)&7 distinct).
__device__ __forceinline__ int slot(int bb, int q) { return q * 64 + ((bb + q) & 63); }

// A = tri & 3 (input misalignment, uniform per block). Tile t loads aligned
// quads covering input columns [64t - A, 64t - A + 4*QPR); compute reads
// positions A..A+63 = output columns [64t, 64t+64).
template <int A>
__device__ __forceinline__ void load_tile(float4* __restrict__ buf,
                                          const float* __restrict__ vrow,
                                          int i, int t, int tid) {
    constexpr int QPR = (A == 0) ? 16 : 17;   // quads per stream
    const int c0 = TJ * t - A;
    #pragma unroll
    for (int s = 0; s < QPR; ++s) {
        int flat = tid + TPB * s;             // bijection over 64*QPR (bb,q)
        int bb, q;
        if (A == 0) { bb = flat >> 4; q = flat & 15; }
        else        { bb = flat / 17; q = flat - bb * 17; }
        int col = c0 + 4 * q;
        int sz  = i - col;                    // floats valid from col (never past
        sz = sz < 0 ? 0 : (sz > 4 ? 4 : sz);  // column i -> never past buffer)
        const float* src = vrow + (size_t)bb * M + (sz > 0 ? col : -A);
        cp16(su32(buf + slot(bb, q)), src, 4 * sz);
    }
}

template <int A>
__device__ __forceinline__ void compute_tile(float4* __restrict__ buf,
                                             int i, int t, int tid, float& rs) {
    const int j0 = TJ * t;
    const bool full = (j0 + TJ <= i);
    #pragma unroll
    for (int c = 0; c < 4; ++c) {             // 16 columns per chunk
        constexpr int NQ = (A == 0) ? 4 : 5;  // quads read: 4c .. 4c+NQ-1
        float e[4 * NQ];
        #pragma unroll
        for (int k = 0; k < NQ; ++k) {
            float4 f = buf[slot(tid, 4 * c + k)];
            e[4*k] = f.x; e[4*k+1] = f.y; e[4*k+2] = f.z; e[4*k+3] = f.w;
        }
        float vv[16];
        if (full) {
            #pragma unroll
            for (int k = 0; k < 16; ++k) vv[k] = chol_step(e[A + k], rs);
        } else {
            #pragma unroll
            for (int k = 0; k < 16; ++k) {
                int j = j0 + 16 * c + k;      // uniform across block
                if (j < i)  vv[k] = chol_step(e[A + k], rs);
                else        vv[k] = (j == i) ? 1.0f : 0.0f;
            }
        }
        // In-place write-back: overwrites quads 4c..4c+3 only (quad 4c+4, still
        // needed by the next chunk when A>0, is untouched).
        #pragma unroll
        for (int k2 = 0; k2 < 4; ++k2)
            buf[slot(tid, 4 * c + k2)] =
                make_float4(vv[4*k2], vv[4*k2+1], vv[4*k2+2], vv[4*k2+3]);
    }
}

__device__ __forceinline__ void store_tile(const float4* __restrict__ buf,
                                           float* __restrict__ orow,
                                           int t, int tid) {
    const int j0 = TJ * t;                    // multiple of 64 -> aligned STG.128
    #pragma unroll
    for (int s = 0; s < 16; ++s) {
        int flat = tid + TPB * s;
        int bb = flat >> 4, q = flat & 15;    // 256B contiguous per bb
        float4 f = buf[slot(bb, q)];
        *reinterpret_cast<float4*>(orow + (size_t)bb * NN + j0 + 4 * q) = f;
    }
}

template <int A>
__device__ void run_rows(const float* __restrict__ vrow, float* __restrict__ orow,
                         int i, int tid, float4* b0, float4* b1) {
    const int nt = (i >> 6) + 1;              // tiles cover [0, 64*nt) ∋ i
    float4* cur = b0;
    float4* nxt = b1;

    load_tile<A>(cur, vrow, i, 0, tid);
    CP_COMMIT();

    float rs = 0.0f;
    for (int t = 0; t < nt; ++t) {
        CP_WAIT0();
        __syncthreads();                      // cur ready; prev store phase done
        if (t + 1 < nt) {                     // prefetch overlaps compute+store
            load_tile<A>(nxt, vrow, i, t + 1, tid);
            CP_COMMIT();
        }
        compute_tile<A>(cur, i, t, tid, rs);
        __syncthreads();                      // outputs visible cross-thread
        store_tile(cur, orow, t, tid);
        float4* tmp = cur; cur = nxt; nxt = tmp;
    }

    // Pure-zero region: columns [64*nt, N), aligned coalesced float4 stores.
    const int zs = nt << 6;
    if (zs < N) {
        const int wrp = tid >> 5, lane = tid & 31;
        const int nzq = (N - zs) >> 2;
        const float4 z4 = make_float4(0.f, 0.f, 0.f, 0.f);
        for (int bb = wrp; bb < TPB; bb += 2) {
            float4* o4 = reinterpret_cast<float4*>(orow + (size_t)bb * NN + zs);
            for (int q = lane; q < nzq; q += 32) o4[q] = z4;
        }
    }
}

__global__ void __launch_bounds__(TPB)
chol_from_z_kernel(const float* __restrict__ vec, float* __restrict__ out) {
    __shared__ float4 bufA[1088];             // 17*64 quads = 17408 B each
    __shared__ float4 bufB[1088];

    const int i   = (N - 1) - (int)blockIdx.x;   // longest rows first
    const int b0  = (int)blockIdx.y * TPB;
    const int tid = (int)threadIdx.x;
    const int tri = (i * (i - 1)) >> 1;

    const float* vrow = vec + (size_t)b0 * M + tri;
    float* orow = out + ((size_t)b0 * N + i) * (size_t)N;

    switch (tri & 3) {                        // uniform across the block
        case 0:  run_rows<0>(vrow, orow, i, tid, bufA, bufB); break;
        case 1:  run_rows<1>(vrow, orow, i, tid, bufA, bufB); break;
        case 2:  run_rows<2>(vrow, orow, i, tid, bufA, bufB); break;
        default: run_rows<3>(vrow, orow, i, tid, bufA, bufB); break;
    }
}

extern "C" void kernel_launch(void* const* d_in, const int* in_sizes, int n_in,
                              void* d_out, int out_size) {
    const float* vec = (const float*)d_in[0];
    float* out = (float*)d_out;
    dim3 grid(N, B / TPB);                    // (256, 8)
    chol_from_z_kernel<<<grid, TPB>>>(vec, out);
}

// round 13
// speedup vs baseline: 1.6583x; 1.6583x over previous
#include <cuda_runtime.h>
#include <cuda_bf16.h>
#include <cstdint>

static constexpr int N   = 256;
static constexpr int B   = 512;
static constexpr int M   = N * (N - 1) / 2;   // 32640
static constexpr int TPB = 128;               // 4 warps; warp owns 32 batches
static constexpr int SS  = 36;                // smem row stride: 16B-aligned + conflict-free
static constexpr int WSTRIDE = 32 * SS;       // private smem floats per warp
static constexpr long long NN = (long long)N * N;

__device__ __forceinline__ float sqrt_approx(float x) {
    float r;
    asm("sqrt.approx.f32 %0, %1;" : "=f"(r) : "f"(x));
    return r;
}

// Reference step; x2 = fma(-z2, rs, z2) = z2*(1-rs) in one rounding. Identical
// to the reference wherever rs >= 0.5 (Sterbenz: 1-rs exact), which covers the
// deep-column plateau; <= 1 ulp relative difference below. Chain: 8 cyc/elem.
__device__ __forceinline__ float chol_step(float z, float& rs) {
    float z2 = __fmul_rn(z, z);
    float x2 = __fmaf_rn(-z2, rs, z2);
    rs       = __fadd_rn(rs, x2);
    return copysignf(sqrt_approx(x2), z);
}

__global__ void __launch_bounds__(TPB, 4)
chol_from_z_kernel(const float* __restrict__ vec, float* __restrict__ out) {
    __shared__ float sw[4 * WSTRIDE];         // 18.4 KB; warp-private slices

    const int i    = (N - 1) - (int)blockIdx.x;   // longest rows first
    const int wrp  = (int)threadIdx.x >> 5;
    const int lane = (int)threadIdx.x & 31;
    const int bw   = (int)blockIdx.y * TPB + wrp * 32;  // warp's batch base
    const int tri  = (i * (i - 1)) >> 1;

    const float* __restrict__ vbase = vec + (size_t)bw * M + tri;
    float* __restrict__ obase = out + ((size_t)bw * N + i) * (size_t)N;
    float* __restrict__ s = sw + wrp * WSTRIDE;   // [32 batches][SS]

    const int ntiles = (i >> 5) + 1;          // last tile is mixed
    float r[32];                              // prefetch regs: r[k] = z[bw+k][j0+lane]

    // ---- prologue: load tile 0 (coalesced 128B per LDG; predicated at scan end)
    #pragma unroll
    for (int k = 0; k < 32; ++k)
        r[k] = (lane < i) ? vbase[(size_t)k * M + lane] : 0.0f;

    float rs = 0.0f;
    for (int t = 0; t < ntiles; ++t) {
        const int j0 = t << 5;
        const bool more = (t + 1 < ntiles);

        // ---- stage current tile into this warp's smem slice ----
        #pragma unroll
        for (int k = 0; k < 32; ++k)
            s[k * SS + lane] = r[k];
        __syncwarp();

        // ---- prefetch tile t+1 (overlaps the compute chain below) ----
        if (more) {
            const int j1 = j0 + 32;
            #pragma unroll
            for (int k = 0; k < 32; ++k) {
                int j = j1 + lane;
                r[k] = (j < i) ? vbase[(size_t)k * M + j] : 0.0f;
            }
        }

        // ---- compute: lane = batch, serial chain over 32 columns ----
        {
            float v[32];
            #pragma unroll
            for (int q = 0; q < 8; ++q) {     // LDS.128: 16B-aligned (SS=36), clean banks
                float4 f = *reinterpret_cast<const float4*>(&s[lane * SS + 4 * q]);
                v[4*q] = f.x; v[4*q+1] = f.y; v[4*q+2] = f.z; v[4*q+3] = f.w;
            }
            if (j0 + 32 <= i) {               // full tile
                #pragma unroll
                for (int jj = 0; jj < 32; ++jj) v[jj] = chol_step(v[jj], rs);
            } else {                          // mixed: scan tail, diag 1, zeros
                #pragma unroll
                for (int jj = 0; jj < 32; ++jj) {
                    int j = j0 + jj;          // uniform across warp
                    if (j < i)  v[jj] = chol_step(v[jj], rs);
                    else        v[jj] = (j == i) ? 1.0f : 0.0f;
                }
            }
            #pragma unroll
            for (int q = 0; q < 8; ++q)
                *reinterpret_cast<float4*>(&s[lane * SS + 4 * q]) =
                    make_float4(v[4*q], v[4*q+1], v[4*q+2], v[4*q+3]);
        }
        __syncwarp();

        // ---- store tile: LDS.128 conflict-free, STG.128 (4x128B lines/op) ----
        #pragma unroll
        for (int st = 0; st < 8; ++st) {
            int flat = lane + 32 * st;        // 256 quads: (batch k, quad q)
            int k = flat >> 3, q = flat & 7;
            float4 f = *reinterpret_cast<const float4*>(&s[k * SS + 4 * q]);
            *reinterpret_cast<float4*>(&obase[(size_t)k * NN + j0 + 4 * q]) = f;
        }
        __syncwarp();                         // slice reused next iteration
    }

    // ---- pure-zero region: columns [32*ntiles, N), aligned float4 stores ----
    const int zs = ntiles << 5;
    if (zs < N) {
        const int nzq = (N - zs) >> 2;
        const float4 z4 = make_float4(0.f, 0.f, 0.f, 0.f);
        for (int k = 0; k < 32; ++k) {
            float4* o4 = reinterpret_cast<float4*>(&obase[(size_t)k * NN + zs]);
            for (int q = lane; q < nzq; q += 32)
                o4[q] = z4;
        }
    }
}

extern "C" void kernel_launch(void* const* d_in, const int* in_sizes, int n_in,
                              void* d_out, int out_size) {
    const float* vec = (const float*)d_in[0];
    float* out = (float*)d_out;
    dim3 grid(N, B / TPB);                    // (256, 4) -> 1024 blocks, 4096 warps
    chol_from_z_kernel<<<grid, TPB>>>(vec, out);
}